// round 7
// baseline (speedup 1.0000x reference)
#include <cuda_runtime.h>
#include <math.h>

namespace {
constexpr int Bsz  = 8;
constexpr int Lsz  = 1024;
constexpr int Hsz  = 8;
constexpr int Esz  = 64;
constexpr int HIST = 512;
constexpr float SCALE = 0.125f;   // 1/sqrt(64), folded into Q at load
constexpr int BM = 128;           // q rows per block
constexpr int BN = 64;            // key tile
constexpr int SK = 68;            // smem row stride (floats) for all tiles
constexpr int SM_P = BM * SK;     // Q staging, then P
constexpr int SM_T = BN * SK;     // one K or Vt buffer
constexpr int SMEM_BYTES = (SM_P + 4 * SM_T + 2 * BM) * 4;   // ~103 KB
}

__device__ __forceinline__ unsigned f2tf(float x) {
    unsigned u; asm("cvt.rna.tf32.f32 %0, %1;" : "=r"(u) : "f"(x)); return u;
}
__device__ __forceinline__ float f2tf_f(float x) { return __uint_as_float(f2tf(x)); }

__device__ __forceinline__ void mma_tf32(float* d, const unsigned* a, unsigned b0, unsigned b1) {
    asm("mma.sync.aligned.m16n8k8.row.col.f32.tf32.tf32.f32 "
        "{%0,%1,%2,%3},{%4,%5,%6,%7},{%8,%9},{%0,%1,%2,%3};"
        : "+f"(d[0]), "+f"(d[1]), "+f"(d[2]), "+f"(d[3])
        : "r"(a[0]), "r"(a[1]), "r"(a[2]), "r"(a[3]), "r"(b0), "r"(b1));
}
__device__ __forceinline__ void ldsm4(unsigned* r, unsigned addr) {
    asm volatile("ldmatrix.sync.aligned.m8n8.x4.shared.b16 {%0,%1,%2,%3}, [%4];"
        : "=r"(r[0]), "=r"(r[1]), "=r"(r[2]), "=r"(r[3]) : "r"(addr));
}

__global__ __launch_bounds__(256, 1)
void fftcc_attn_kernel(const float* __restrict__ Q,  const float* __restrict__ K,
                       const float* __restrict__ V,  const float* __restrict__ QD,
                       const float* __restrict__ KD, const float* __restrict__ VD,
                       float* __restrict__ Out)
{
    extern __shared__ float smem[];
    float* Ps   = smem;                      // [BM][SK]: Q staging, then P
    float* KsB0 = Ps + SM_P;                 // K double buffer
    float* KsB1 = KsB0 + SM_T;
    float* VtB0 = KsB1 + SM_T;               // Vt (transposed V) double buffer
    float* VtB1 = VtB0 + SM_T;
    float* dSs  = VtB1 + SM_T;               // [BM] diag scores (pre-scaled)
    float* pdS  = dSs + BM;                  // [BM] diag probabilities

    const unsigned ps_u  = (unsigned)__cvta_generic_to_shared(Ps);
    const unsigned ks_u[2] = { (unsigned)__cvta_generic_to_shared(KsB0),
                               (unsigned)__cvta_generic_to_shared(KsB1) };
    const unsigned vt_u[2] = { (unsigned)__cvta_generic_to_shared(VtB0),
                               (unsigned)__cvta_generic_to_shared(VtB1) };
    float* KsBp[2] = { KsB0, KsB1 };
    float* VtBp[2] = { VtB0, VtB1 };

    const int bh = blockIdx.y;
    const int b  = bh >> 3;
    const int h  = bh & 7;
    const int m0 = (int)(gridDim.x - 1 - blockIdx.x) * BM;   // heaviest first
    const int tid  = threadIdx.x;
    const int w    = tid >> 5;
    const int lane = tid & 31;
    const int rr   = lane >> 2;              // 0..7
    const int qi   = lane & 3;               // 0..3
    const int rs   = Hsz * Esz;              // 512
    const int base = (b * Lsz * Hsz + h) * Esz;
    const bool has_diag = (m0 >= HIST);
    const int wb = w * 16;                   // warp's first local row

    // ldmatrix per-lane addressing
    const int g  = lane >> 3, r8 = lane & 7;
    const int b_row  = ((g >> 1) << 3) + r8;       // B-frags (K, Vt)
    const int b_col4 = (g & 1) * 4;
    const int a_row  = ((g & 1) << 3) + r8;        // A-frags (Q, P)
    const int a_col4 = (g >> 1) * 4;
    const unsigned a_base = ps_u + (unsigned)(((wb + a_row) * SK + a_col4) * 4);
    const unsigned b_off  = (unsigned)((b_row * SK + b_col4) * 4);

    // ---- Load Q (q_eff), pre-scaled, tf32, into Ps staging ----
    #pragma unroll
    for (int it = 0; it < 8; ++it) {
        const int idx = it * 256 + tid;          // 0..2047
        const int r  = idx >> 4;
        const int ce = idx & 15;
        const int l  = m0 + r;
        const float* src = (l < HIST) ? Q : QD;
        const float4 v = *reinterpret_cast<const float4*>(src + base + l * rs + (ce << 2));
        *reinterpret_cast<float4*>(Ps + r * SK + (ce << 2)) =
            make_float4(f2tf_f(v.x * SCALE), f2tf_f(v.y * SCALE),
                        f2tf_f(v.z * SCALE), f2tf_f(v.w * SCALE));
    }
    // ---- Diagonal raw scores (full fp32, pre-scaled) ----
    if (has_diag && tid < BM) {
        const int l = m0 + tid;
        const float* qr = QD + base + l * rs;
        const float* kr = KD + base + l * rs;
        float acc = 0.f;
        #pragma unroll
        for (int ce = 0; ce < 16; ++ce) {
            const float4 qv = *reinterpret_cast<const float4*>(qr + (ce << 2));
            const float4 kv = *reinterpret_cast<const float4*>(kr + (ce << 2));
            acc += qv.x * kv.x + qv.y * kv.y + qv.z * kv.z + qv.w * kv.w;
        }
        dSs[tid] = acc * SCALE;
    }
    __syncthreads();

    // ---- Extract Q A-fragments via ldmatrix (held all kernel) ----
    unsigned qa[8][4];
    #pragma unroll
    for (int k = 0; k < 8; ++k) ldsm4(qa[k], a_base + k * 32);
    // (warp-collective ldmatrix done; Ps reusable as P after this, rows are warp-private)

    float o[8][4];
    #pragma unroll
    for (int nf = 0; nf < 8; ++nf)
        #pragma unroll
        for (int c = 0; c < 4; ++c) o[nf][c] = 0.f;
    float mrow0 = -INFINITY, mrow1 = -INFINITY, lsum0 = 0.f, lsum1 = 0.f;

    const int ntiles = (m0 >> 6) + 2;

    // ---- prologue: LDG + STS tile 0 into buffer 0 ----
    float4 kr[4], vr[4];
    const int sIdx = tid & 63;               // V-transpose lane mapping
    const int cph  = tid >> 6;
    {
        const int n0 = 0;
        #pragma unroll
        for (int it = 0; it < 4; ++it) {
            const int idx = it * 256 + tid;
            kr[it] = *reinterpret_cast<const float4*>(K + base + (n0 + (idx >> 4)) * rs + ((idx & 15) << 2));
            vr[it] = *reinterpret_cast<const float4*>(V + base + (n0 + sIdx) * rs + ((cph + 4 * it) << 2));
        }
        #pragma unroll
        for (int it = 0; it < 4; ++it) {
            const int idx = it * 256 + tid;
            *reinterpret_cast<float4*>(KsBp[0] + (idx >> 4) * SK + ((idx & 15) << 2)) =
                make_float4(f2tf_f(kr[it].x), f2tf_f(kr[it].y), f2tf_f(kr[it].z), f2tf_f(kr[it].w));
            const int c = cph + 4 * it;
            VtBp[0][(4 * c + 0) * SK + sIdx] = f2tf_f(vr[it].x);
            VtBp[0][(4 * c + 1) * SK + sIdx] = f2tf_f(vr[it].y);
            VtBp[0][(4 * c + 2) * SK + sIdx] = f2tf_f(vr[it].z);
            VtBp[0][(4 * c + 3) * SK + sIdx] = f2tf_f(vr[it].w);
        }
    }

    const int l0 = m0 + wb + rr;             // global rows of c0/c1
    const int l1 = l0 + 8;                   // global rows of c2/c3

    for (int t = 0; t < ntiles; ++t) {
        __syncthreads();                     // STS(t) visible; all done reading buf(t^1)
        const int buf = t & 1;
        const bool last = (t + 1 == ntiles);

        // ---- issue LDG for next tile (overlapped with compute) ----
        if (!last) {
            const int n1 = (t + 1) << 6;
            #pragma unroll
            for (int it = 0; it < 4; ++it) {
                const int idx = it * 256 + tid;
                kr[it] = *reinterpret_cast<const float4*>(K + base + (n1 + (idx >> 4)) * rs + ((idx & 15) << 2));
                vr[it] = *reinterpret_cast<const float4*>(V + base + (n1 + sIdx) * rs + ((cph + 4 * it) << 2));
            }
        }

        const int n0 = t << 6;
        const bool crossing = (n0 >= m0);
        const bool active = (wb + 15 + m0) >= n0;   // warp has any unmasked row

        if (active) {
            // ---- S = Q @ K^T (ldmatrix B-frags) ----
            float s[8][4];
            #pragma unroll
            for (int nf = 0; nf < 8; ++nf)
                #pragma unroll
                for (int c = 0; c < 4; ++c) s[nf][c] = 0.f;
            #pragma unroll
            for (int nfp = 0; nfp < 4; ++nfp) {
                const unsigned kb = ks_u[buf] + b_off + (unsigned)(nfp * 16 * SK * 4);
                #pragma unroll
                for (int k = 0; k < 8; ++k) {
                    unsigned bb[4];
                    ldsm4(bb, kb + k * 32);
                    mma_tf32(s[2 * nfp],     qa[k], bb[0], bb[1]);
                    mma_tf32(s[2 * nfp + 1], qa[k], bb[2], bb[3]);
                }
            }

            // ---- diag substitution + causal mask ----
            if (crossing) {
                #pragma unroll
                for (int nf = 0; nf < 8; ++nf) {
                    const int col = n0 + nf * 8 + 2 * qi;
                    if (has_diag) {
                        if (col     == l0) s[nf][0] = dSs[l0 - m0];
                        if (col + 1 == l0) s[nf][1] = dSs[l0 - m0];
                        if (col     == l1) s[nf][2] = dSs[l1 - m0];
                        if (col + 1 == l1) s[nf][3] = dSs[l1 - m0];
                    }
                    if (col     > l0) s[nf][0] = -INFINITY;
                    if (col + 1 > l0) s[nf][1] = -INFINITY;
                    if (col     > l1) s[nf][2] = -INFINITY;
                    if (col + 1 > l1) s[nf][3] = -INFINITY;
                }
            }

            // ---- online softmax (quad reductions) ----
            float mx0 = -INFINITY, mx1 = -INFINITY;
            #pragma unroll
            for (int nf = 0; nf < 8; ++nf) {
                mx0 = fmaxf(mx0, fmaxf(s[nf][0], s[nf][1]));
                mx1 = fmaxf(mx1, fmaxf(s[nf][2], s[nf][3]));
            }
            #pragma unroll
            for (int off = 1; off <= 2; off <<= 1) {
                mx0 = fmaxf(mx0, __shfl_xor_sync(0xffffffffu, mx0, off));
                mx1 = fmaxf(mx1, __shfl_xor_sync(0xffffffffu, mx1, off));
            }
            const float nm0 = fmaxf(mrow0, mx0);
            const float nm1 = fmaxf(mrow1, mx1);
            const float corr0 = __expf(mrow0 - nm0);
            const float corr1 = __expf(mrow1 - nm1);
            mrow0 = nm0; mrow1 = nm1;

            float rs0 = 0.f, rs1 = 0.f;
            #pragma unroll
            for (int nf = 0; nf < 8; ++nf) {
                s[nf][0] = __expf(s[nf][0] - nm0);
                s[nf][1] = __expf(s[nf][1] - nm0);
                s[nf][2] = __expf(s[nf][2] - nm1);
                s[nf][3] = __expf(s[nf][3] - nm1);
                rs0 += s[nf][0] + s[nf][1];
                rs1 += s[nf][2] + s[nf][3];
            }
            #pragma unroll
            for (int off = 1; off <= 2; off <<= 1) {
                rs0 += __shfl_xor_sync(0xffffffffu, rs0, off);
                rs1 += __shfl_xor_sync(0xffffffffu, rs1, off);
            }
            lsum0 = lsum0 * corr0 + rs0;
            lsum1 = lsum1 * corr1 + rs1;
            #pragma unroll
            for (int nf = 0; nf < 8; ++nf) {
                o[nf][0] *= corr0; o[nf][1] *= corr0;
                o[nf][2] *= corr1; o[nf][3] *= corr1;
            }

            // ---- capture diag probabilities; store P (tf32, warp-private rows) ----
            if (crossing && has_diag) {
                #pragma unroll
                for (int nf = 0; nf < 8; ++nf) {
                    const int col = n0 + nf * 8 + 2 * qi;
                    if (col     == l0) pdS[l0 - m0] = s[nf][0];
                    if (col + 1 == l0) pdS[l0 - m0] = s[nf][1];
                    if (col     == l1) pdS[l1 - m0] = s[nf][2];
                    if (col + 1 == l1) pdS[l1 - m0] = s[nf][3];
                }
            }
            #pragma unroll
            for (int nf = 0; nf < 8; ++nf) {
                *reinterpret_cast<float2*>(Ps + (wb + rr) * SK + nf * 8 + 2 * qi) =
                    make_float2(f2tf_f(s[nf][0]), f2tf_f(s[nf][1]));
                *reinterpret_cast<float2*>(Ps + (wb + rr + 8) * SK + nf * 8 + 2 * qi) =
                    make_float2(f2tf_f(s[nf][2]), f2tf_f(s[nf][3]));
            }
            __syncwarp();

            // ---- O += P @ V (ldmatrix A and B frags) ----
            #pragma unroll
            for (int k = 0; k < 8; ++k) {
                unsigned pa[4];
                ldsm4(pa, a_base + k * 32);
                const unsigned vb = vt_u[buf] + b_off + (unsigned)(k * 32);
                #pragma unroll
                for (int nfp = 0; nfp < 4; ++nfp) {
                    unsigned bb[4];
                    ldsm4(bb, vb + (unsigned)(nfp * 16 * SK * 4));
                    mma_tf32(o[2 * nfp],     pa, bb[0], bb[1]);
                    mma_tf32(o[2 * nfp + 1], pa, bb[2], bb[3]);
                }
            }
            __syncwarp();
        }

        // ---- STS next tile into other buffer (no barrier needed here) ----
        if (!last) {
            float* Kd = KsBp[buf ^ 1];
            float* Vd = VtBp[buf ^ 1];
            #pragma unroll
            for (int it = 0; it < 4; ++it) {
                const int idx = it * 256 + tid;
                *reinterpret_cast<float4*>(Kd + (idx >> 4) * SK + ((idx & 15) << 2)) =
                    make_float4(f2tf_f(kr[it].x), f2tf_f(kr[it].y), f2tf_f(kr[it].z), f2tf_f(kr[it].w));
                const int c = cph + 4 * it;
                Vd[(4 * c + 0) * SK + sIdx] = f2tf_f(vr[it].x);
                Vd[(4 * c + 1) * SK + sIdx] = f2tf_f(vr[it].y);
                Vd[(4 * c + 2) * SK + sIdx] = f2tf_f(vr[it].z);
                Vd[(4 * c + 3) * SK + sIdx] = f2tf_f(vr[it].w);
            }
        }
    }

    // ---- epilogue: diag value substitution, normalize, store ----
    __syncwarp();                            // pdS written by sibling lanes
    const float inv0 = 1.0f / lsum0;
    const float inv1 = 1.0f / lsum1;
    const float pd0 = has_diag ? pdS[l0 - m0] : 0.f;
    const float pd1 = has_diag ? pdS[l1 - m0] : 0.f;

    #pragma unroll
    for (int nf = 0; nf < 8; ++nf) {
        const int e = nf * 8 + 2 * qi;
        float v00 = o[nf][0], v01 = o[nf][1], v10 = o[nf][2], v11 = o[nf][3];
        if (has_diag) {
            const float2 vd0 = *reinterpret_cast<const float2*>(VD + base + l0 * rs + e);
            const float2 vo0 = *reinterpret_cast<const float2*>(V  + base + l0 * rs + e);
            const float2 vd1 = *reinterpret_cast<const float2*>(VD + base + l1 * rs + e);
            const float2 vo1 = *reinterpret_cast<const float2*>(V  + base + l1 * rs + e);
            v00 += pd0 * (vd0.x - vo0.x);
            v01 += pd0 * (vd0.y - vo0.y);
            v10 += pd1 * (vd1.x - vo1.x);
            v11 += pd1 * (vd1.y - vo1.y);
        }
        *reinterpret_cast<float2*>(Out + base + l0 * rs + e) = make_float2(v00 * inv0, v01 * inv0);
        *reinterpret_cast<float2*>(Out + base + l1 * rs + e) = make_float2(v10 * inv1, v11 * inv1);
    }
}

extern "C" void kernel_launch(void* const* d_in, const int* in_sizes, int n_in,
                              void* d_out, int out_size)
{
    const float* Q  = (const float*)d_in[0];
    const float* K  = (const float*)d_in[1];
    const float* V  = (const float*)d_in[2];
    const float* QD = (const float*)d_in[3];
    const float* KD = (const float*)d_in[4];
    const float* VD = (const float*)d_in[5];
    float* Out = (float*)d_out;

    cudaFuncSetAttribute(fftcc_attn_kernel,
                         cudaFuncAttributeMaxDynamicSharedMemorySize, SMEM_BYTES);
    dim3 grid(Lsz / BM, Bsz * Hsz);    // (8, 64)
    fftcc_attn_kernel<<<grid, 256, SMEM_BYTES>>>(Q, K, V, QD, KD, VD, Out);
}